// round 15
// baseline (speedup 1.0000x reference)
#include <cuda_runtime.h>
#include <cuda_bf16.h>
#include <cstdint>

#define NN     8192
#define RR     8
#define NB     30
#define HH     128
#define OO     64
#define CC     128
#define W1COLS 1152
#define W2COLS 640
#define NSEG   (NN * RR)

// ---------------- scratch (device globals; no allocation allowed) ----------------
__device__ __align__(16) float g_Wbig1[(size_t)NN * W1COLS];
__device__ __align__(16) float g_xWb1 [(size_t)NN * W1COLS];
__device__ __align__(16) float g_sums1[(size_t)NSEG * HH];
__device__ __align__(16) int   g_cnt  [NSEG];
__device__ __align__(16) float g_h1   [(size_t)NN * HH];
__device__ __align__(16) float g_Wbig2[(size_t)HH * W2COLS];
__device__ __align__(16) float g_xWb2 [(size_t)NN * W2COLS];
__device__ __align__(16) float g_sums2[(size_t)NSEG * OO];
__device__ __align__(16) float g_h2   [(size_t)NN * OO];
__device__ int g_is32;

__device__ __align__(16) unsigned short g_Ah [(size_t)NN * NN];
__device__ __align__(16) unsigned short g_Al [(size_t)NN * NN];
__device__ __align__(16) unsigned short g_BhT[(size_t)W1COLS * NN];
__device__ __align__(16) unsigned short g_BlT[(size_t)W1COLS * NN];

// ---------------- index dtype detection + safe accessor ----------------
__global__ void detect_dtype(const unsigned* w, int nwords) {
    int i = blockIdx.x * blockDim.x + threadIdx.x;
    unsigned v = 0;
    if (i < nwords && (i & 1)) {
        v = w[i];
    }
    if (__syncthreads_or(v != 0u)) {
        if (threadIdx.x == 0) {
            atomicOr(&g_is32, 1);
        }
    }
}

__device__ __forceinline__ int load_idx(const void* p, long long i) {
    if (g_is32) {
        return ((const int*)p)[i];
    }
    return (int)((const long long*)p)[i];
}

// ---------------- low-level helpers ----------------
__device__ __forceinline__ unsigned smem_u32(const void* p) {
    unsigned a;
    asm("{ .reg .u64 t; cvta.to.shared.u64 t, %1; cvt.u32.u64 %0, t; }"
        : "=r"(a) : "l"(p));
    return a;
}

__device__ __forceinline__ void cp_async16(unsigned s, const void* g) {
    asm volatile("cp.async.cg.shared.global [%0], [%1], 16;"
                 :: "r"(s), "l"(g) : "memory");
}

__device__ __forceinline__ void cp_commit() {
    asm volatile("cp.async.commit_group;" ::: "memory");
}

__device__ __forceinline__ void cp_wait0() {
    asm volatile("cp.async.wait_group 0;" ::: "memory");
}

__device__ __forceinline__ void ldmx4(unsigned& r0, unsigned& r1, unsigned& r2,
                                      unsigned& r3, unsigned a) {
    asm volatile("ldmatrix.sync.aligned.m8n8.x4.shared.b16 {%0,%1,%2,%3}, [%4];"
                 : "=r"(r0), "=r"(r1), "=r"(r2), "=r"(r3) : "r"(a));
}

__device__ __forceinline__ void mma16816(float* d, unsigned a0, unsigned a1,
                                         unsigned a2, unsigned a3,
                                         unsigned b0, unsigned b1) {
    asm volatile("mma.sync.aligned.m16n8k16.row.col.f32.bf16.bf16.f32 "
                 "{%0,%1,%2,%3}, {%4,%5,%6,%7}, {%8,%9}, {%0,%1,%2,%3};"
                 : "+f"(d[0]), "+f"(d[1]), "+f"(d[2]), "+f"(d[3])
                 : "r"(a0), "r"(a1), "r"(a2), "r"(a3), "r"(b0), "r"(b1));
}

// SW64 swizzle for 64-byte rows: conflict-free 8-row column access
__device__ __forceinline__ unsigned swz64(unsigned b) {
    return b ^ ((b >> 3) & 0x30u);
}

// vector reductions (PTX ISA 8.1, sm_90+; plain sm_100-legal)
__device__ __forceinline__ void red_add_v4(float* d, float4 v) {
    asm volatile("red.global.add.v4.f32 [%0], {%1, %2, %3, %4};"
                 :: "l"(d), "f"(v.x), "f"(v.y), "f"(v.z), "f"(v.w) : "memory");
}

__device__ __forceinline__ void red_add_v2(float* d, float2 v) {
    asm volatile("red.global.add.v2.f32 [%0], {%1, %2};"
                 :: "l"(d), "f"(v.x), "f"(v.y) : "memory");
}

__device__ __forceinline__ unsigned long long ffma2(unsigned long long a,
                                                    unsigned long long b,
                                                    unsigned long long c) {
    unsigned long long d;
    asm("fma.rn.f32x2 %0, %1, %2, %3;" : "=l"(d) : "l"(a), "l"(b), "l"(c));
    return d;
}

__device__ __forceinline__ unsigned long long dup2(float x) {
    unsigned long long d;
    asm("mov.b64 %0, {%1, %1};" : "=l"(d) : "f"(x));
    return d;
}

// ---------------- zero scratch ----------------
__global__ void zero_all() {
    int i = blockIdx.x * blockDim.x + threadIdx.x;
    float4 z = make_float4(0.f, 0.f, 0.f, 0.f);
    if (i == 0) {
        g_is32 = 0;
    }
    if (i < NSEG * HH / 4) {
        ((float4*)g_sums1)[i] = z;
    }
    if (i < NSEG * OO / 4) {
        ((float4*)g_sums2)[i] = z;
    }
    if (i < NSEG / 4) {
        ((int4*)g_cnt)[i] = make_int4(0, 0, 0, 0);
    }
    if (i < HH * W2COLS / 4) {
        ((float4*)g_Wbig2)[i] = z;
    }
}

// ---------------- split x into hi/lo bf16 ----------------
__global__ void splitX(const float* x) {
    size_t i = (size_t)blockIdx.x * blockDim.x + threadIdx.x;
    float4 v = ((const float4*)x)[i];
    float vv[4];
    vv[0] = v.x; vv[1] = v.y; vv[2] = v.z; vv[3] = v.w;
    unsigned short h[4];
    unsigned short l[4];
    #pragma unroll
    for (int q = 0; q < 4; q++) {
        __nv_bfloat16 hb = __float2bfloat16(vv[q]);
        h[q] = __bfloat16_as_ushort(hb);
        float r = vv[q] - __bfloat162float(hb);
        l[q] = __bfloat16_as_ushort(__float2bfloat16(r));
    }
    ((ushort4*)g_Ah)[i] = make_ushort4(h[0], h[1], h[2], h[3]);
    ((ushort4*)g_Al)[i] = make_ushort4(l[0], l[1], l[2], l[3]);
}

// ---------------- build Wbig1 = [comp1 x basis1 | root1] ----------------
__global__ void build_W1(const float* basis1, const float* comp1,
                         const float* root1) {
    __shared__ float sc[RR * NB];
    int tid = threadIdx.x;
    if (tid < RR * NB) {
        sc[tid] = comp1[tid];
    }
    __syncthreads();
    int idx = blockIdx.x * blockDim.x + tid;
    int n = idx >> 7;
    int h = idx & 127;
    float s[RR];
    #pragma unroll
    for (int r = 0; r < RR; r++) {
        s[r] = 0.f;
    }
    for (int b = 0; b < NB; b++) {
        float v = basis1[((size_t)b * NN + n) * HH + h];
        #pragma unroll
        for (int r = 0; r < RR; r++) {
            s[r] = fmaf(sc[r * NB + b], v, s[r]);
        }
    }
    float* orow = g_Wbig1 + (size_t)n * W1COLS;
    #pragma unroll
    for (int r = 0; r < RR; r++) {
        orow[r * HH + h] = s[r];
    }
    orow[RR * HH + h] = root1[(size_t)n * HH + h];
}

// ---------------- transpose + split W1 -> BhT/BlT [1152][8192] ----------------
__global__ void splitW1() {
    __shared__ float t[32][33];
    int c0 = blockIdx.x * 32;
    int k0 = blockIdx.y * 32;
    int tx = threadIdx.x;
    int ty = threadIdx.y;
    for (int i = ty; i < 32; i += 8) {
        t[i][tx] = g_Wbig1[(size_t)(k0 + i) * W1COLS + c0 + tx];
    }
    __syncthreads();
    for (int i = ty; i < 32; i += 8) {
        float v = t[tx][i];
        __nv_bfloat16 hb = __float2bfloat16(v);
        float r = v - __bfloat162float(hb);
        size_t o = (size_t)(c0 + i) * NN + k0 + tx;
        g_BhT[o] = __bfloat16_as_ushort(hb);
        g_BlT[o] = __bfloat16_as_ushort(__float2bfloat16(r));
    }
}

// ---------------- HMMA bf16 GEMM1: 2-stage, ONE barrier per chunk ----------------
// g_xWb1[8192,1152] = Ah*Bh + Ah*Bl + Al*Bh. Virtual K = 3*8192, 768 chunks of 32.
// 128x128 CTA tile, 256 threads (2x4 warps, 64x32 each). Loop structure:
//   wait_group 0 -> barrier -> prefetch(c+1 -> stage (c+1)&1) -> compute(c, c&1)
// Stage (c+1)&1 was last read by compute(c-1); every thread finished that
// before this iteration's barrier. Static SMEM stays 32768 B (48K is poison).
#define CHUNKS 768

__device__ __forceinline__ void hload(unsigned smBase, int st, int c,
                                      int bm, int bn, int tid) {
    int pass = c >> 8;
    int kk = (c & 255) << 5;
    const unsigned short* A = (pass < 2) ? g_Ah : g_Al;
    const unsigned short* B = (pass == 1) ? g_BlT : g_BhT;
    unsigned base = smBase + (unsigned)st * 16384u;
    #pragma unroll
    for (int i = 0; i < 2; i++) {
        int g = tid + i * 256;
        int row = g >> 2;
        int cc = (g & 3) * 16;
        unsigned so = swz64((unsigned)(row * 64 + cc));
        cp_async16(base + so,
                   (const char*)(A + (size_t)(bm + row) * NN + kk) + cc);
        cp_async16(base + 8192u + so,
                   (const char*)(B + (size_t)(bn + row) * NN + kk) + cc);
    }
}

__global__ void __launch_bounds__(256, 2) hmma_gemm1() {
    __shared__ __align__(1024) char sm[2][16384];
    const int tid = threadIdx.x;
    const int wid = tid >> 5;
    const int lane = tid & 31;
    const int warpM = wid >> 2;
    const int warpN = wid & 3;
    const int bm = blockIdx.y * 128;
    const int bn = blockIdx.x * 128;
    const unsigned smBase = smem_u32(&sm[0][0]);

    const int lq = lane >> 3;
    const int lr = lane & 7;
    const int aRow = warpM * 64 + lr + (lq & 1) * 8;
    const int aCol = (lq >> 1) * 16;
    const int bRow = warpN * 32 + (lq >> 1) * 8 + lr;
    const int bCol = (lq & 1) * 16;

    float acc[4][4][4];
    #pragma unroll
    for (int mi = 0; mi < 4; mi++) {
        #pragma unroll
        for (int ni = 0; ni < 4; ni++) {
            #pragma unroll
            for (int q = 0; q < 4; q++) {
                acc[mi][ni][q] = 0.f;
            }
        }
    }

    hload(smBase, 0, 0, bm, bn, tid);
    cp_commit();

    for (int c = 0; c < CHUNKS; c++) {
        cp_wait0();
        __syncthreads();
        if (c + 1 < CHUNKS) {
            hload(smBase, (c + 1) & 1, c + 1, bm, bn, tid);
            cp_commit();
        }
        unsigned sA = smBase + (unsigned)(c & 1) * 16384u;
        unsigned sB = sA + 8192u;
        #pragma unroll
        for (int ks = 0; ks < 2; ks++) {
            unsigned a[4][4];
            unsigned b[2][4];
            #pragma unroll
            for (int mi = 0; mi < 4; mi++) {
                ldmx4(a[mi][0], a[mi][1], a[mi][2], a[mi][3],
                      sA + swz64((unsigned)((aRow + mi * 16) * 64 + ks * 32 + aCol)));
            }
            #pragma unroll
            for (int nj = 0; nj < 2; nj++) {
                ldmx4(b[nj][0], b[nj][1], b[nj][2], b[nj][3],
                      sB + swz64((unsigned)((bRow + nj * 16) * 64 + ks * 32 + bCol)));
            }
            #pragma unroll
            for (int mi = 0; mi < 4; mi++) {
                #pragma unroll
                for (int ni = 0; ni < 4; ni++) {
                    mma16816(acc[mi][ni],
                             a[mi][0], a[mi][1], a[mi][2], a[mi][3],
                             b[ni >> 1][(ni & 1) * 2],
                             b[ni >> 1][(ni & 1) * 2 + 1]);
                }
            }
        }
    }

    #pragma unroll
    for (int mi = 0; mi < 4; mi++) {
        int row = bm + warpM * 64 + mi * 16 + (lane >> 2);
        #pragma unroll
        for (int ni = 0; ni < 4; ni++) {
            int col = bn + warpN * 32 + ni * 8 + (lane & 3) * 2;
            float2 v01;
            v01.x = acc[mi][ni][0];
            v01.y = acc[mi][ni][1];
            float2 v23;
            v23.x = acc[mi][ni][2];
            v23.y = acc[mi][ni][3];
            *(float2*)&g_xWb1[(size_t)row * W1COLS + col] = v01;
            *(float2*)&g_xWb1[(size_t)(row + 8) * W1COLS + col] = v23;
        }
    }
}

// ---------------- build Wbig2 = [comp2 x basis2 | root2 | 0pad] ----------------
__global__ void build_W2(const float* basis2, const float* comp2,
                         const float* root2) {
    __shared__ float sc[RR * NB];
    int tid = threadIdx.x;
    if (tid < RR * NB) {
        sc[tid] = comp2[tid];
    }
    __syncthreads();
    int idx = blockIdx.x * blockDim.x + tid;
    if (idx >= HH * OO) {
        return;
    }
    int k = idx >> 6;
    int o = idx & 63;
    float s[RR];
    #pragma unroll
    for (int r = 0; r < RR; r++) {
        s[r] = 0.f;
    }
    for (int b = 0; b < NB; b++) {
        float v = basis2[((size_t)b * HH + k) * OO + o];
        #pragma unroll
        for (int r = 0; r < RR; r++) {
            s[r] = fmaf(sc[r * NB + b], v, s[r]);
        }
    }
    float* orow = g_Wbig2 + (size_t)k * W2COLS;
    #pragma unroll
    for (int r = 0; r < RR; r++) {
        orow[r * OO + o] = s[r];
    }
    orow[RR * OO + o] = root2[(size_t)k * OO + o];
}

// ---------------- SIMT GEMM (layer 2), 128x128 tile, BK=16, f32x2 FMA ----------------
__global__ void __launch_bounds__(256, 2) sgemm_l2() {
    const float* A = g_h1;
    const float* B = g_Wbig2;
    float* C = g_xWb2;
    const int K = HH;
    const int lda = HH;
    const int ldb = W2COLS;
    const int ldc = W2COLS;
    __shared__ float As[16][132];
    __shared__ float Bs[16][128];

    const int tid = threadIdx.x;
    const int tx = tid & 15;
    const int ty = tid >> 4;
    const size_t bm = (size_t)blockIdx.y * 128;
    const size_t bn = (size_t)blockIdx.x * 128;

    const int arow = tid >> 2;
    const int acol = (tid & 3) * 4;
    const float* Ap = A + (bm + arow) * (size_t)lda + acol;
    const int brow = tid >> 5;
    const int bcol = (tid & 31) * 4;
    const float* Bp = B + (size_t)brow * ldb + bn + bcol;

    unsigned long long acc[8][4];
    #pragma unroll
    for (int i = 0; i < 8; i++) {
        #pragma unroll
        for (int j = 0; j < 4; j++) {
            acc[i][j] = 0ull;
        }
    }

    for (int k0 = 0; k0 < K; k0 += 16) {
        float4 a0 = *(const float4*)(Ap + k0);
        float4 a1 = *(const float4*)(Ap + (size_t)64 * lda + k0);
        float4 b0 = *(const float4*)(Bp + (size_t)k0 * ldb);
        float4 b1 = *(const float4*)(Bp + (size_t)(k0 + 8) * ldb);
        __syncthreads();
        As[acol + 0][arow] = a0.x;
        As[acol + 1][arow] = a0.y;
        As[acol + 2][arow] = a0.z;
        As[acol + 3][arow] = a0.w;
        As[acol + 0][arow + 64] = a1.x;
        As[acol + 1][arow + 64] = a1.y;
        As[acol + 2][arow + 64] = a1.z;
        As[acol + 3][arow + 64] = a1.w;
        *(float4*)&Bs[brow][bcol] = b0;
        *(float4*)&Bs[brow + 8][bcol] = b1;
        __syncthreads();
        #pragma unroll
        for (int k = 0; k < 16; k++) {
            float4 aA = *(const float4*)&As[k][ty * 8];
            float4 aB = *(const float4*)&As[k][ty * 8 + 4];
            ulonglong2 blo = *(const ulonglong2*)&Bs[k][tx * 8];
            ulonglong2 bhi = *(const ulonglong2*)&Bs[k][tx * 8 + 4];
            float av[8];
            av[0] = aA.x; av[1] = aA.y; av[2] = aA.z; av[3] = aA.w;
            av[4] = aB.x; av[5] = aB.y; av[6] = aB.z; av[7] = aB.w;
            unsigned long long bv[4];
            bv[0] = blo.x; bv[1] = blo.y; bv[2] = bhi.x; bv[3] = bhi.y;
            #pragma unroll
            for (int i = 0; i < 8; i++) {
                unsigned long long ad = dup2(av[i]);
                #pragma unroll
                for (int j = 0; j < 4; j++) {
                    acc[i][j] = ffma2(ad, bv[j], acc[i][j]);
                }
            }
        }
    }
    #pragma unroll
    for (int i = 0; i < 8; i++) {
        float* crow = C + (bm + ty * 8 + i) * (size_t)ldc + bn + tx * 8;
        ulonglong2 s0;
        s0.x = acc[i][0];
        s0.y = acc[i][1];
        ulonglong2 s1;
        s1.x = acc[i][2];
        s1.y = acc[i][3];
        *(ulonglong2*)(crow) = s0;
        *(ulonglong2*)(crow + 4) = s1;
    }
}

// ---------------- edge count per (dst, relation) segment ----------------
__global__ void count_edges(const void* ei, const void* et, int E) {
    int e = blockIdx.x * blockDim.x + threadIdx.x;
    if (e >= E) {
        return;
    }
    int dst = load_idx(ei, (long long)E + e) & (NN - 1);
    int r = load_idx(et, e) & (RR - 1);
    atomicAdd(&g_cnt[dst * RR + r], 1);
}

// ---------------- scatter layer 1: warp per edge, red.v4 per lane ----------------
__global__ void scatter1(const void* ei, const void* et, int E) {
    int gt = blockIdx.x * blockDim.x + threadIdx.x;
    int e = gt >> 5;
    int lane = gt & 31;
    if (e >= E) {
        return;
    }
    int src = load_idx(ei, e) & (NN - 1);
    int dst = load_idx(ei, (long long)E + e) & (NN - 1);
    int r = load_idx(et, e) & (RR - 1);
    float4 v = *(const float4*)(g_xWb1 + (size_t)src * W1COLS + r * HH + lane * 4);
    float* d = g_sums1 + ((size_t)(dst * RR + r)) * HH + lane * 4;
    red_add_v4(d, v);
}

// ---------------- combine layer 1: mean + root + bias + relu ----------------
__global__ void combine1(const float* bias1) {
    int idx = blockIdx.x * blockDim.x + threadIdx.x;
    int n = idx >> 7;
    int h = idx & 127;
    float s = 0.f;
    #pragma unroll
    for (int r = 0; r < RR; r++) {
        int seg = n * RR + r;
        int c = g_cnt[seg];
        float inv = 1.f / (float)(c > 1 ? c : 1);
        s += g_sums1[(size_t)seg * HH + h] * inv;
    }
    s += g_xWb1[(size_t)n * W1COLS + RR * HH + h] + bias1[h];
    g_h1[idx] = fmaxf(s, 0.f);
}

// ---------------- scatter layer 2: warp per edge, red.v2 per lane ----------------
__global__ void scatter2(const void* ei, const void* et, int E) {
    int gt = blockIdx.x * blockDim.x + threadIdx.x;
    int e = gt >> 5;
    int lane = gt & 31;
    if (e >= E) {
        return;
    }
    int src = load_idx(ei, e) & (NN - 1);
    int dst = load_idx(ei, (long long)E + e) & (NN - 1);
    int r = load_idx(et, e) & (RR - 1);
    float2 v = *(const float2*)(g_xWb2 + (size_t)src * W2COLS + r * OO + lane * 2);
    float* d = g_sums2 + ((size_t)(dst * RR + r)) * OO + lane * 2;
    red_add_v2(d, v);
}

// ---------------- combine layer 2: mean + root + bias ----------------
__global__ void combine2(const float* bias2) {
    int idx = blockIdx.x * blockDim.x + threadIdx.x;
    int n = idx >> 6;
    int o = idx & 63;
    float s = 0.f;
    #pragma unroll
    for (int r = 0; r < RR; r++) {
        int seg = n * RR + r;
        int c = g_cnt[seg];
        float inv = 1.f / (float)(c > 1 ? c : 1);
        s += g_sums2[(size_t)seg * OO + o] * inv;
    }
    s += g_xWb2[(size_t)n * W2COLS + RR * OO + o] + bias2[o];
    g_h2[idx] = s;
}

// ---------------- classifier ----------------
__global__ void classifier(const float* w, const float* b, float* out) {
    __shared__ float hrow[OO];
    int n = blockIdx.x;
    int c = threadIdx.x;
    if (c < OO) {
        hrow[c] = g_h2[(size_t)n * OO + c];
    }
    __syncthreads();
    float acc = b[c];
    #pragma unroll
    for (int o = 0; o < OO; o++) {
        acc = fmaf(hrow[o], w[o * CC + c], acc);
    }
    out[(size_t)n * CC + c] = acc;
}

// ---------------- launch ----------------
// hmma_gemm1 stays 4th so the ncu capture window profiles it.
extern "C" void kernel_launch(void* const* d_in, const int* in_sizes, int n_in,
                              void* d_out, int out_size) {
    const float* x      = (const float*)d_in[0];
    const void*  ei     = d_in[1];
    const void*  et     = d_in[2];
    const float* basis1 = (const float*)d_in[3];
    const float* comp1  = (const float*)d_in[4];
    const float* root1  = (const float*)d_in[5];
    const float* bias1  = (const float*)d_in[6];
    const float* basis2 = (const float*)d_in[7];
    const float* comp2  = (const float*)d_in[8];
    const float* root2  = (const float*)d_in[9];
    const float* bias2  = (const float*)d_in[10];
    const float* clfw   = (const float*)d_in[11];
    const float* clfb   = (const float*)d_in[12];
    float* out = (float*)d_out;
    const int E = in_sizes[2];

    splitX<<<(int)(((size_t)NN * NN / 4) / 256), 256>>>(x);
    build_W1<<<NN * HH / 256, 256>>>(basis1, comp1, root1);
    splitW1<<<dim3(W1COLS / 32, NN / 32), dim3(32, 8)>>>();
    hmma_gemm1<<<dim3(W1COLS / 128, NN / 128), 256>>>();

    zero_all<<<(NSEG * HH / 4 + 255) / 256, 256>>>();
    detect_dtype<<<(2 * E + 255) / 256, 256>>>((const unsigned*)ei, 2 * E);
    count_edges<<<(E + 255) / 256, 256>>>(ei, et, E);

    scatter1<<<(E * 32 + 255) / 256, 256>>>(ei, et, E);
    combine1<<<NN * HH / 256, 256>>>(bias1);

    build_W2<<<(HH * OO + 255) / 256, 256>>>(basis2, comp2, root2);
    sgemm_l2<<<dim3(W2COLS / 128, NN / 128), 256>>>();
    scatter2<<<(E * 32 + 255) / 256, 256>>>(ei, et, E);
    combine2<<<NN * OO / 256, 256>>>(bias2);

    classifier<<<NN, CC>>>(clfw, clfb, out);
}

// round 16
// speedup vs baseline: 1.0721x; 1.0721x over previous
#include <cuda_runtime.h>
#include <cuda_bf16.h>
#include <cstdint>

#define NN     8192
#define RR     8
#define NB     30
#define HH     128
#define OO     64
#define CC     128
#define W1COLS 1152
#define W2COLS 640
#define NSEG   (NN * RR)

// ---------------- scratch (device globals; no allocation allowed) ----------------
__device__ __align__(16) float g_Wbig1[(size_t)NN * W1COLS];
__device__ __align__(16) float g_xWb1 [(size_t)NN * W1COLS];
__device__ __align__(16) float g_sums1[(size_t)NSEG * HH];
__device__ __align__(16) int   g_cnt  [NSEG];
__device__ __align__(16) float g_h1   [(size_t)NN * HH];
__device__ __align__(16) float g_Wbig2[(size_t)HH * W2COLS];
__device__ __align__(16) float g_xWb2 [(size_t)NN * W2COLS];
__device__ __align__(16) float g_sums2[(size_t)NSEG * OO];
__device__ __align__(16) float g_h2   [(size_t)NN * OO];
__device__ int g_is32;

__device__ __align__(16) unsigned short g_Ah [(size_t)NN * NN];
__device__ __align__(16) unsigned short g_Al [(size_t)NN * NN];
__device__ __align__(16) unsigned short g_BhT[(size_t)W1COLS * NN];
__device__ __align__(16) unsigned short g_BlT[(size_t)W1COLS * NN];

// ---------------- index dtype detection + safe accessor ----------------
__global__ void detect_dtype(const unsigned* w, int nwords) {
    int i = blockIdx.x * blockDim.x + threadIdx.x;
    unsigned v = 0;
    if (i < nwords && (i & 1)) {
        v = w[i];
    }
    if (__syncthreads_or(v != 0u)) {
        if (threadIdx.x == 0) {
            atomicOr(&g_is32, 1);
        }
    }
}

__device__ __forceinline__ int load_idx(const void* p, long long i) {
    if (g_is32) {
        return ((const int*)p)[i];
    }
    return (int)((const long long*)p)[i];
}

// ---------------- low-level helpers ----------------
__device__ __forceinline__ unsigned smem_u32(const void* p) {
    unsigned a;
    asm("{ .reg .u64 t; cvta.to.shared.u64 t, %1; cvt.u32.u64 %0, t; }"
        : "=r"(a) : "l"(p));
    return a;
}

__device__ __forceinline__ void cp_async16(unsigned s, const void* g) {
    asm volatile("cp.async.cg.shared.global [%0], [%1], 16;"
                 :: "r"(s), "l"(g) : "memory");
}

__device__ __forceinline__ void cp_commit() {
    asm volatile("cp.async.commit_group;" ::: "memory");
}

__device__ __forceinline__ void cp_wait1() {
    asm volatile("cp.async.wait_group 1;" ::: "memory");
}

__device__ __forceinline__ void cp_wait0() {
    asm volatile("cp.async.wait_group 0;" ::: "memory");
}

__device__ __forceinline__ void ldmx4(unsigned& r0, unsigned& r1, unsigned& r2,
                                      unsigned& r3, unsigned a) {
    asm volatile("ldmatrix.sync.aligned.m8n8.x4.shared.b16 {%0,%1,%2,%3}, [%4];"
                 : "=r"(r0), "=r"(r1), "=r"(r2), "=r"(r3) : "r"(a));
}

__device__ __forceinline__ void mma16816(float* d, unsigned a0, unsigned a1,
                                         unsigned a2, unsigned a3,
                                         unsigned b0, unsigned b1) {
    asm volatile("mma.sync.aligned.m16n8k16.row.col.f32.bf16.bf16.f32 "
                 "{%0,%1,%2,%3}, {%4,%5,%6,%7}, {%8,%9}, {%0,%1,%2,%3};"
                 : "+f"(d[0]), "+f"(d[1]), "+f"(d[2]), "+f"(d[3])
                 : "r"(a0), "r"(a1), "r"(a2), "r"(a3), "r"(b0), "r"(b1));
}

// SW64 swizzle for 64-byte rows: conflict-free 8-row column access
__device__ __forceinline__ unsigned swz64(unsigned b) {
    return b ^ ((b >> 3) & 0x30u);
}

// vector reductions (PTX ISA 8.1, sm_90+; plain sm_100-legal)
__device__ __forceinline__ void red_add_v4(float* d, float4 v) {
    asm volatile("red.global.add.v4.f32 [%0], {%1, %2, %3, %4};"
                 :: "l"(d), "f"(v.x), "f"(v.y), "f"(v.z), "f"(v.w) : "memory");
}

__device__ __forceinline__ void red_add_v2(float* d, float2 v) {
    asm volatile("red.global.add.v2.f32 [%0], {%1, %2};"
                 :: "l"(d), "f"(v.x), "f"(v.y) : "memory");
}

__device__ __forceinline__ unsigned long long ffma2(unsigned long long a,
                                                    unsigned long long b,
                                                    unsigned long long c) {
    unsigned long long d;
    asm("fma.rn.f32x2 %0, %1, %2, %3;" : "=l"(d) : "l"(a), "l"(b), "l"(c));
    return d;
}

__device__ __forceinline__ unsigned long long dup2(float x) {
    unsigned long long d;
    asm("mov.b64 %0, {%1, %1};" : "=l"(d) : "f"(x));
    return d;
}

// ---------------- zero scratch ----------------
__global__ void zero_all() {
    int i = blockIdx.x * blockDim.x + threadIdx.x;
    float4 z = make_float4(0.f, 0.f, 0.f, 0.f);
    if (i == 0) {
        g_is32 = 0;
    }
    if (i < NSEG * HH / 4) {
        ((float4*)g_sums1)[i] = z;
    }
    if (i < NSEG * OO / 4) {
        ((float4*)g_sums2)[i] = z;
    }
    if (i < NSEG / 4) {
        ((int4*)g_cnt)[i] = make_int4(0, 0, 0, 0);
    }
    if (i < HH * W2COLS / 4) {
        ((float4*)g_Wbig2)[i] = z;
    }
}

// ---------------- split x into hi/lo bf16 ----------------
__global__ void splitX(const float* x) {
    size_t i = (size_t)blockIdx.x * blockDim.x + threadIdx.x;
    float4 v = ((const float4*)x)[i];
    float vv[4];
    vv[0] = v.x; vv[1] = v.y; vv[2] = v.z; vv[3] = v.w;
    unsigned short h[4];
    unsigned short l[4];
    #pragma unroll
    for (int q = 0; q < 4; q++) {
        __nv_bfloat16 hb = __float2bfloat16(vv[q]);
        h[q] = __bfloat16_as_ushort(hb);
        float r = vv[q] - __bfloat162float(hb);
        l[q] = __bfloat16_as_ushort(__float2bfloat16(r));
    }
    ((ushort4*)g_Ah)[i] = make_ushort4(h[0], h[1], h[2], h[3]);
    ((ushort4*)g_Al)[i] = make_ushort4(l[0], l[1], l[2], l[3]);
}

// ---------------- build Wbig1 = [comp1 x basis1 | root1] ----------------
__global__ void build_W1(const float* basis1, const float* comp1,
                         const float* root1) {
    __shared__ float sc[RR * NB];
    int tid = threadIdx.x;
    if (tid < RR * NB) {
        sc[tid] = comp1[tid];
    }
    __syncthreads();
    int idx = blockIdx.x * blockDim.x + tid;
    int n = idx >> 7;
    int h = idx & 127;
    float s[RR];
    #pragma unroll
    for (int r = 0; r < RR; r++) {
        s[r] = 0.f;
    }
    for (int b = 0; b < NB; b++) {
        float v = basis1[((size_t)b * NN + n) * HH + h];
        #pragma unroll
        for (int r = 0; r < RR; r++) {
            s[r] = fmaf(sc[r * NB + b], v, s[r]);
        }
    }
    float* orow = g_Wbig1 + (size_t)n * W1COLS;
    #pragma unroll
    for (int r = 0; r < RR; r++) {
        orow[r * HH + h] = s[r];
    }
    orow[RR * HH + h] = root1[(size_t)n * HH + h];
}

// ---------------- transpose + split W1 -> BhT/BlT [1152][8192] ----------------
__global__ void splitW1() {
    __shared__ float t[32][33];
    int c0 = blockIdx.x * 32;
    int k0 = blockIdx.y * 32;
    int tx = threadIdx.x;
    int ty = threadIdx.y;
    for (int i = ty; i < 32; i += 8) {
        t[i][tx] = g_Wbig1[(size_t)(k0 + i) * W1COLS + c0 + tx];
    }
    __syncthreads();
    for (int i = ty; i < 32; i += 8) {
        float v = t[tx][i];
        __nv_bfloat16 hb = __float2bfloat16(v);
        float r = v - __bfloat162float(hb);
        size_t o = (size_t)(c0 + i) * NN + k0 + tx;
        g_BhT[o] = __bfloat16_as_ushort(hb);
        g_BlT[o] = __bfloat16_as_ushort(__float2bfloat16(r));
    }
}

// ---------------- HMMA bf16 GEMM1: 3-stage DYNAMIC smem, 1 barrier/chunk ----------------
// g_xWb1[8192,1152] = Ah*Bh + Ah*Bl + Al*Bh. Virtual K = 3*8192, 768 chunks of 32.
// 128x128 CTA tile, 256 threads (2x4 warps, 64x32 each). Loop:
//   wait_group 1 -> barrier -> prefetch(c+2 -> stage (c+2)%3) -> compute(c)
// Two groups stay in flight (R13-depth) with one barrier per chunk (R15-count).
// Stage (c+2)%3 was last read by compute(c-1), finished before this barrier.
// 3 x 16384 = 49152 B as DYNAMIC smem (static 49152 is the container-killer;
// 49152 dynamic == default limit, no attribute call needed).
#define CHUNKS 768
#define GSTAGE 16384
#define GSMEM  (3 * GSTAGE)

__device__ __forceinline__ void hload(unsigned smBase, int st, int c,
                                      int bm, int bn, int tid) {
    int pass = c >> 8;
    int kk = (c & 255) << 5;
    const unsigned short* A = (pass < 2) ? g_Ah : g_Al;
    const unsigned short* B = (pass == 1) ? g_BlT : g_BhT;
    unsigned base = smBase + (unsigned)st * (unsigned)GSTAGE;
    #pragma unroll
    for (int i = 0; i < 2; i++) {
        int g = tid + i * 256;
        int row = g >> 2;
        int cc = (g & 3) * 16;
        unsigned so = swz64((unsigned)(row * 64 + cc));
        cp_async16(base + so,
                   (const char*)(A + (size_t)(bm + row) * NN + kk) + cc);
        cp_async16(base + 8192u + so,
                   (const char*)(B + (size_t)(bn + row) * NN + kk) + cc);
    }
}

__global__ void __launch_bounds__(256, 2) hmma_gemm1() {
    extern __shared__ __align__(1024) char gsm[];
    const int tid = threadIdx.x;
    const int wid = tid >> 5;
    const int lane = tid & 31;
    const int warpM = wid >> 2;
    const int warpN = wid & 3;
    const int bm = blockIdx.y * 128;
    const int bn = blockIdx.x * 128;
    const unsigned smBase = smem_u32(gsm);

    const int lq = lane >> 3;
    const int lr = lane & 7;
    const int aRow = warpM * 64 + lr + (lq & 1) * 8;
    const int aCol = (lq >> 1) * 16;
    const int bRow = warpN * 32 + (lq >> 1) * 8 + lr;
    const int bCol = (lq & 1) * 16;

    float acc[4][4][4];
    #pragma unroll
    for (int mi = 0; mi < 4; mi++) {
        #pragma unroll
        for (int ni = 0; ni < 4; ni++) {
            #pragma unroll
            for (int q = 0; q < 4; q++) {
                acc[mi][ni][q] = 0.f;
            }
        }
    }

    // prologue: stages 0 and 1 in flight
    hload(smBase, 0, 0, bm, bn, tid);
    cp_commit();
    hload(smBase, 1, 1, bm, bn, tid);
    cp_commit();

    int st = 0;
    for (int c = 0; c < CHUNKS; c++) {
        if (c + 1 < CHUNKS) {
            cp_wait1();
        } else {
            cp_wait0();
        }
        __syncthreads();
        if (c + 2 < CHUNKS) {
            int st2 = st + 2;
            if (st2 >= 3) {
                st2 -= 3;
            }
            hload(smBase, st2, c + 2, bm, bn, tid);
            cp_commit();
        }
        unsigned sA = smBase + (unsigned)st * (unsigned)GSTAGE;
        unsigned sB = sA + 8192u;
        #pragma unroll
        for (int ks = 0; ks < 2; ks++) {
            unsigned a[4][4];
            unsigned b[2][4];
            #pragma unroll
            for (int mi = 0; mi < 4; mi++) {
                ldmx4(a[mi][0], a[mi][1], a[mi][2], a[mi][3],
                      sA + swz64((unsigned)((aRow + mi * 16) * 64 + ks * 32 + aCol)));
            }
            #pragma unroll
            for (int nj = 0; nj < 2; nj++) {
                ldmx4(b[nj][0], b[nj][1], b[nj][2], b[nj][3],
                      sB + swz64((unsigned)((bRow + nj * 16) * 64 + ks * 32 + bCol)));
            }
            #pragma unroll
            for (int mi = 0; mi < 4; mi++) {
                #pragma unroll
                for (int ni = 0; ni < 4; ni++) {
                    mma16816(acc[mi][ni],
                             a[mi][0], a[mi][1], a[mi][2], a[mi][3],
                             b[ni >> 1][(ni & 1) * 2],
                             b[ni >> 1][(ni & 1) * 2 + 1]);
                }
            }
        }
        st = st + 1;
        if (st >= 3) {
            st = 0;
        }
    }

    #pragma unroll
    for (int mi = 0; mi < 4; mi++) {
        int row = bm + warpM * 64 + mi * 16 + (lane >> 2);
        #pragma unroll
        for (int ni = 0; ni < 4; ni++) {
            int col = bn + warpN * 32 + ni * 8 + (lane & 3) * 2;
            float2 v01;
            v01.x = acc[mi][ni][0];
            v01.y = acc[mi][ni][1];
            float2 v23;
            v23.x = acc[mi][ni][2];
            v23.y = acc[mi][ni][3];
            *(float2*)&g_xWb1[(size_t)row * W1COLS + col] = v01;
            *(float2*)&g_xWb1[(size_t)(row + 8) * W1COLS + col] = v23;
        }
    }
}

// ---------------- build Wbig2 = [comp2 x basis2 | root2 | 0pad] ----------------
__global__ void build_W2(const float* basis2, const float* comp2,
                         const float* root2) {
    __shared__ float sc[RR * NB];
    int tid = threadIdx.x;
    if (tid < RR * NB) {
        sc[tid] = comp2[tid];
    }
    __syncthreads();
    int idx = blockIdx.x * blockDim.x + tid;
    if (idx >= HH * OO) {
        return;
    }
    int k = idx >> 6;
    int o = idx & 63;
    float s[RR];
    #pragma unroll
    for (int r = 0; r < RR; r++) {
        s[r] = 0.f;
    }
    for (int b = 0; b < NB; b++) {
        float v = basis2[((size_t)b * HH + k) * OO + o];
        #pragma unroll
        for (int r = 0; r < RR; r++) {
            s[r] = fmaf(sc[r * NB + b], v, s[r]);
        }
    }
    float* orow = g_Wbig2 + (size_t)k * W2COLS;
    #pragma unroll
    for (int r = 0; r < RR; r++) {
        orow[r * OO + o] = s[r];
    }
    orow[RR * OO + o] = root2[(size_t)k * OO + o];
}

// ---------------- SIMT GEMM (layer 2), 128x128 tile, BK=16, f32x2 FMA ----------------
__global__ void __launch_bounds__(256, 2) sgemm_l2() {
    const float* A = g_h1;
    const float* B = g_Wbig2;
    float* C = g_xWb2;
    const int K = HH;
    const int lda = HH;
    const int ldb = W2COLS;
    const int ldc = W2COLS;
    __shared__ float As[16][132];
    __shared__ float Bs[16][128];

    const int tid = threadIdx.x;
    const int tx = tid & 15;
    const int ty = tid >> 4;
    const size_t bm = (size_t)blockIdx.y * 128;
    const size_t bn = (size_t)blockIdx.x * 128;

    const int arow = tid >> 2;
    const int acol = (tid & 3) * 4;
    const float* Ap = A + (bm + arow) * (size_t)lda + acol;
    const int brow = tid >> 5;
    const int bcol = (tid & 31) * 4;
    const float* Bp = B + (size_t)brow * ldb + bn + bcol;

    unsigned long long acc[8][4];
    #pragma unroll
    for (int i = 0; i < 8; i++) {
        #pragma unroll
        for (int j = 0; j < 4; j++) {
            acc[i][j] = 0ull;
        }
    }

    for (int k0 = 0; k0 < K; k0 += 16) {
        float4 a0 = *(const float4*)(Ap + k0);
        float4 a1 = *(const float4*)(Ap + (size_t)64 * lda + k0);
        float4 b0 = *(const float4*)(Bp + (size_t)k0 * ldb);
        float4 b1 = *(const float4*)(Bp + (size_t)(k0 + 8) * ldb);
        __syncthreads();
        As[acol + 0][arow] = a0.x;
        As[acol + 1][arow] = a0.y;
        As[acol + 2][arow] = a0.z;
        As[acol + 3][arow] = a0.w;
        As[acol + 0][arow + 64] = a1.x;
        As[acol + 1][arow + 64] = a1.y;
        As[acol + 2][arow + 64] = a1.z;
        As[acol + 3][arow + 64] = a1.w;
        *(float4*)&Bs[brow][bcol] = b0;
        *(float4*)&Bs[brow + 8][bcol] = b1;
        __syncthreads();
        #pragma unroll
        for (int k = 0; k < 16; k++) {
            float4 aA = *(const float4*)&As[k][ty * 8];
            float4 aB = *(const float4*)&As[k][ty * 8 + 4];
            ulonglong2 blo = *(const ulonglong2*)&Bs[k][tx * 8];
            ulonglong2 bhi = *(const ulonglong2*)&Bs[k][tx * 8 + 4];
            float av[8];
            av[0] = aA.x; av[1] = aA.y; av[2] = aA.z; av[3] = aA.w;
            av[4] = aB.x; av[5] = aB.y; av[6] = aB.z; av[7] = aB.w;
            unsigned long long bv[4];
            bv[0] = blo.x; bv[1] = blo.y; bv[2] = bhi.x; bv[3] = bhi.y;
            #pragma unroll
            for (int i = 0; i < 8; i++) {
                unsigned long long ad = dup2(av[i]);
                #pragma unroll
                for (int j = 0; j < 4; j++) {
                    acc[i][j] = ffma2(ad, bv[j], acc[i][j]);
                }
            }
        }
    }
    #pragma unroll
    for (int i = 0; i < 8; i++) {
        float* crow = C + (bm + ty * 8 + i) * (size_t)ldc + bn + tx * 8;
        ulonglong2 s0;
        s0.x = acc[i][0];
        s0.y = acc[i][1];
        ulonglong2 s1;
        s1.x = acc[i][2];
        s1.y = acc[i][3];
        *(ulonglong2*)(crow) = s0;
        *(ulonglong2*)(crow + 4) = s1;
    }
}

// ---------------- edge count per (dst, relation) segment ----------------
__global__ void count_edges(const void* ei, const void* et, int E) {
    int e = blockIdx.x * blockDim.x + threadIdx.x;
    if (e >= E) {
        return;
    }
    int dst = load_idx(ei, (long long)E + e) & (NN - 1);
    int r = load_idx(et, e) & (RR - 1);
    atomicAdd(&g_cnt[dst * RR + r], 1);
}

// ---------------- scatter layer 1: warp per edge, red.v4 per lane ----------------
__global__ void scatter1(const void* ei, const void* et, int E) {
    int gt = blockIdx.x * blockDim.x + threadIdx.x;
    int e = gt >> 5;
    int lane = gt & 31;
    if (e >= E) {
        return;
    }
    int src = load_idx(ei, e) & (NN - 1);
    int dst = load_idx(ei, (long long)E + e) & (NN - 1);
    int r = load_idx(et, e) & (RR - 1);
    float4 v = *(const float4*)(g_xWb1 + (size_t)src * W1COLS + r * HH + lane * 4);
    float* d = g_sums1 + ((size_t)(dst * RR + r)) * HH + lane * 4;
    red_add_v4(d, v);
}

// ---------------- combine layer 1: mean + root + bias + relu ----------------
__global__ void combine1(const float* bias1) {
    int idx = blockIdx.x * blockDim.x + threadIdx.x;
    int n = idx >> 7;
    int h = idx & 127;
    float s = 0.f;
    #pragma unroll
    for (int r = 0; r < RR; r++) {
        int seg = n * RR + r;
        int c = g_cnt[seg];
        float inv = 1.f / (float)(c > 1 ? c : 1);
        s += g_sums1[(size_t)seg * HH + h] * inv;
    }
    s += g_xWb1[(size_t)n * W1COLS + RR * HH + h] + bias1[h];
    g_h1[idx] = fmaxf(s, 0.f);
}

// ---------------- scatter layer 2: warp per edge, red.v2 per lane ----------------
__global__ void scatter2(const void* ei, const void* et, int E) {
    int gt = blockIdx.x * blockDim.x + threadIdx.x;
    int e = gt >> 5;
    int lane = gt & 31;
    if (e >= E) {
        return;
    }
    int src = load_idx(ei, e) & (NN - 1);
    int dst = load_idx(ei, (long long)E + e) & (NN - 1);
    int r = load_idx(et, e) & (RR - 1);
    float2 v = *(const float2*)(g_xWb2 + (size_t)src * W2COLS + r * OO + lane * 2);
    float* d = g_sums2 + ((size_t)(dst * RR + r)) * OO + lane * 2;
    red_add_v2(d, v);
}

// ---------------- combine layer 2: mean + root + bias ----------------
__global__ void combine2(const float* bias2) {
    int idx = blockIdx.x * blockDim.x + threadIdx.x;
    int n = idx >> 6;
    int o = idx & 63;
    float s = 0.f;
    #pragma unroll
    for (int r = 0; r < RR; r++) {
        int seg = n * RR + r;
        int c = g_cnt[seg];
        float inv = 1.f / (float)(c > 1 ? c : 1);
        s += g_sums2[(size_t)seg * OO + o] * inv;
    }
    s += g_xWb2[(size_t)n * W2COLS + RR * OO + o] + bias2[o];
    g_h2[idx] = s;
}

// ---------------- classifier ----------------
__global__ void classifier(const float* w, const float* b, float* out) {
    __shared__ float hrow[OO];
    int n = blockIdx.x;
    int c = threadIdx.x;
    if (c < OO) {
        hrow[c] = g_h2[(size_t)n * OO + c];
    }
    __syncthreads();
    float acc = b[c];
    #pragma unroll
    for (int o = 0; o < OO; o++) {
        acc = fmaf(hrow[o], w[o * CC + c], acc);
    }
    out[(size_t)n * CC + c] = acc;
}

// ---------------- launch ----------------
// hmma_gemm1 stays 4th so the ncu capture window profiles it.
extern "C" void kernel_launch(void* const* d_in, const int* in_sizes, int n_in,
                              void* d_out, int out_size) {
    const float* x      = (const float*)d_in[0];
    const void*  ei     = d_in[1];
    const void*  et     = d_in[2];
    const float* basis1 = (const float*)d_in[3];
    const float* comp1  = (const float*)d_in[4];
    const float* root1  = (const float*)d_in[5];
    const float* bias1  = (const float*)d_in[6];
    const float* basis2 = (const float*)d_in[7];
    const float* comp2  = (const float*)d_in[8];
    const float* root2  = (const float*)d_in[9];
    const float* bias2  = (const float*)d_in[10];
    const float* clfw   = (const float*)d_in[11];
    const float* clfb   = (const float*)d_in[12];
    float* out = (float*)d_out;
    const int E = in_sizes[2];

    splitX<<<(int)(((size_t)NN * NN / 4) / 256), 256>>>(x);
    build_W1<<<NN * HH / 256, 256>>>(basis1, comp1, root1);
    splitW1<<<dim3(W1COLS / 32, NN / 32), dim3(32, 8)>>>();
    hmma_gemm1<<<dim3(W1COLS / 128, NN / 128), 256, GSMEM>>>();

    zero_all<<<(NSEG * HH / 4 + 255) / 256, 256>>>();
    detect_dtype<<<(2 * E + 255) / 256, 256>>>((const unsigned*)ei, 2 * E);
    count_edges<<<(E + 255) / 256, 256>>>(ei, et, E);

    scatter1<<<(E * 32 + 255) / 256, 256>>>(ei, et, E);
    combine1<<<NN * HH / 256, 256>>>(bias1);

    build_W2<<<(HH * OO + 255) / 256, 256>>>(basis2, comp2, root2);
    sgemm_l2<<<dim3(W2COLS / 128, NN / 128), 256>>>();
    scatter2<<<(E * 32 + 255) / 256, 256>>>(ei, et, E);
    combine2<<<NN * OO / 256, 256>>>(bias2);

    classifier<<<NN, CC>>>(clfw, clfb, out);
}

// round 17
// speedup vs baseline: 1.0839x; 1.0110x over previous
#include <cuda_runtime.h>
#include <cuda_bf16.h>
#include <cstdint>

#define NN     8192
#define RR     8
#define NB     30
#define HH     128
#define OO     64
#define CC     128
#define W1COLS 1152
#define W2COLS 640
#define NSEG   (NN * RR)

// ---------------- scratch (device globals; no allocation allowed) ----------------
__device__ __align__(16) float g_Wbig1[(size_t)NN * W1COLS];
__device__ __align__(16) float g_xWb1 [(size_t)NN * W1COLS];
__device__ __align__(16) float g_sums1[(size_t)NSEG * HH];
__device__ __align__(16) int   g_cnt  [NSEG];
__device__ __align__(16) float g_h1   [(size_t)NN * HH];
__device__ __align__(16) float g_Wbig2[(size_t)HH * W2COLS];
__device__ __align__(16) float g_xWb2 [(size_t)NN * W2COLS];
__device__ __align__(16) float g_sums2[(size_t)NSEG * OO];
__device__ __align__(16) float g_h2   [(size_t)NN * OO];
__device__ int g_is32;

__device__ __align__(16) unsigned short g_Ah [(size_t)NN * NN];
__device__ __align__(16) unsigned short g_Al [(size_t)NN * NN];
__device__ __align__(16) unsigned short g_BhT[(size_t)W1COLS * NN];
__device__ __align__(16) unsigned short g_BlT[(size_t)W1COLS * NN];

// ---------------- index dtype detection + safe accessor ----------------
__global__ void detect_dtype(const unsigned* w, int nwords) {
    int i = blockIdx.x * blockDim.x + threadIdx.x;
    unsigned v = 0;
    if (i < nwords && (i & 1)) {
        v = w[i];
    }
    if (__syncthreads_or(v != 0u)) {
        if (threadIdx.x == 0) {
            atomicOr(&g_is32, 1);
        }
    }
}

__device__ __forceinline__ int load_idx(const void* p, long long i) {
    if (g_is32) {
        return ((const int*)p)[i];
    }
    return (int)((const long long*)p)[i];
}

// ---------------- low-level helpers ----------------
__device__ __forceinline__ unsigned smem_u32(const void* p) {
    unsigned a;
    asm("{ .reg .u64 t; cvta.to.shared.u64 t, %1; cvt.u32.u64 %0, t; }"
        : "=r"(a) : "l"(p));
    return a;
}

__device__ __forceinline__ void cp_async16(unsigned s, const void* g) {
    asm volatile("cp.async.cg.shared.global [%0], [%1], 16;"
                 :: "r"(s), "l"(g) : "memory");
}

__device__ __forceinline__ void cp_commit() {
    asm volatile("cp.async.commit_group;" ::: "memory");
}

__device__ __forceinline__ void cp_wait1() {
    asm volatile("cp.async.wait_group 1;" ::: "memory");
}

__device__ __forceinline__ void cp_wait0() {
    asm volatile("cp.async.wait_group 0;" ::: "memory");
}

__device__ __forceinline__ void ldmx4(unsigned& r0, unsigned& r1, unsigned& r2,
                                      unsigned& r3, unsigned a) {
    asm volatile("ldmatrix.sync.aligned.m8n8.x4.shared.b16 {%0,%1,%2,%3}, [%4];"
                 : "=r"(r0), "=r"(r1), "=r"(r2), "=r"(r3) : "r"(a));
}

__device__ __forceinline__ void mma16816(float* d, unsigned a0, unsigned a1,
                                         unsigned a2, unsigned a3,
                                         unsigned b0, unsigned b1) {
    asm volatile("mma.sync.aligned.m16n8k16.row.col.f32.bf16.bf16.f32 "
                 "{%0,%1,%2,%3}, {%4,%5,%6,%7}, {%8,%9}, {%0,%1,%2,%3};"
                 : "+f"(d[0]), "+f"(d[1]), "+f"(d[2]), "+f"(d[3])
                 : "r"(a0), "r"(a1), "r"(a2), "r"(a3), "r"(b0), "r"(b1));
}

// SW128 swizzle for 128-byte rows: conflict-free 8-row column access
__device__ __forceinline__ unsigned swz128(unsigned b) {
    return b ^ ((b >> 3) & 0x70u);
}

// vector reductions (PTX ISA 8.1, sm_90+; plain sm_100-legal)
__device__ __forceinline__ void red_add_v4(float* d, float4 v) {
    asm volatile("red.global.add.v4.f32 [%0], {%1, %2, %3, %4};"
                 :: "l"(d), "f"(v.x), "f"(v.y), "f"(v.z), "f"(v.w) : "memory");
}

__device__ __forceinline__ void red_add_v2(float* d, float2 v) {
    asm volatile("red.global.add.v2.f32 [%0], {%1, %2};"
                 :: "l"(d), "f"(v.x), "f"(v.y) : "memory");
}

__device__ __forceinline__ unsigned long long ffma2(unsigned long long a,
                                                    unsigned long long b,
                                                    unsigned long long c) {
    unsigned long long d;
    asm("fma.rn.f32x2 %0, %1, %2, %3;" : "=l"(d) : "l"(a), "l"(b), "l"(c));
    return d;
}

__device__ __forceinline__ unsigned long long dup2(float x) {
    unsigned long long d;
    asm("mov.b64 %0, {%1, %1};" : "=l"(d) : "f"(x));
    return d;
}

// ---------------- zero scratch ----------------
__global__ void zero_all() {
    int i = blockIdx.x * blockDim.x + threadIdx.x;
    float4 z = make_float4(0.f, 0.f, 0.f, 0.f);
    if (i == 0) {
        g_is32 = 0;
    }
    if (i < NSEG * HH / 4) {
        ((float4*)g_sums1)[i] = z;
    }
    if (i < NSEG * OO / 4) {
        ((float4*)g_sums2)[i] = z;
    }
    if (i < NSEG / 4) {
        ((int4*)g_cnt)[i] = make_int4(0, 0, 0, 0);
    }
    if (i < HH * W2COLS / 4) {
        ((float4*)g_Wbig2)[i] = z;
    }
}

// ---------------- split x into hi/lo bf16 ----------------
__global__ void splitX(const float* x) {
    size_t i = (size_t)blockIdx.x * blockDim.x + threadIdx.x;
    float4 v = ((const float4*)x)[i];
    float vv[4];
    vv[0] = v.x; vv[1] = v.y; vv[2] = v.z; vv[3] = v.w;
    unsigned short h[4];
    unsigned short l[4];
    #pragma unroll
    for (int q = 0; q < 4; q++) {
        __nv_bfloat16 hb = __float2bfloat16(vv[q]);
        h[q] = __bfloat16_as_ushort(hb);
        float r = vv[q] - __bfloat162float(hb);
        l[q] = __bfloat16_as_ushort(__float2bfloat16(r));
    }
    ((ushort4*)g_Ah)[i] = make_ushort4(h[0], h[1], h[2], h[3]);
    ((ushort4*)g_Al)[i] = make_ushort4(l[0], l[1], l[2], l[3]);
}

// ---------------- build Wbig1 = [comp1 x basis1 | root1] ----------------
__global__ void build_W1(const float* basis1, const float* comp1,
                         const float* root1) {
    __shared__ float sc[RR * NB];
    int tid = threadIdx.x;
    if (tid < RR * NB) {
        sc[tid] = comp1[tid];
    }
    __syncthreads();
    int idx = blockIdx.x * blockDim.x + tid;
    int n = idx >> 7;
    int h = idx & 127;
    float s[RR];
    #pragma unroll
    for (int r = 0; r < RR; r++) {
        s[r] = 0.f;
    }
    for (int b = 0; b < NB; b++) {
        float v = basis1[((size_t)b * NN + n) * HH + h];
        #pragma unroll
        for (int r = 0; r < RR; r++) {
            s[r] = fmaf(sc[r * NB + b], v, s[r]);
        }
    }
    float* orow = g_Wbig1 + (size_t)n * W1COLS;
    #pragma unroll
    for (int r = 0; r < RR; r++) {
        orow[r * HH + h] = s[r];
    }
    orow[RR * HH + h] = root1[(size_t)n * HH + h];
}

// ---------------- transpose + split W1 -> BhT/BlT [1152][8192] ----------------
__global__ void splitW1() {
    __shared__ float t[32][33];
    int c0 = blockIdx.x * 32;
    int k0 = blockIdx.y * 32;
    int tx = threadIdx.x;
    int ty = threadIdx.y;
    for (int i = ty; i < 32; i += 8) {
        t[i][tx] = g_Wbig1[(size_t)(k0 + i) * W1COLS + c0 + tx];
    }
    __syncthreads();
    for (int i = ty; i < 32; i += 8) {
        float v = t[tx][i];
        __nv_bfloat16 hb = __float2bfloat16(v);
        float r = v - __bfloat162float(hb);
        size_t o = (size_t)(c0 + i) * NN + k0 + tx;
        g_BhT[o] = __bfloat16_as_ushort(hb);
        g_BlT[o] = __bfloat16_as_ushort(__float2bfloat16(r));
    }
}

// ---------------- HMMA bf16 GEMM1: 3-stage dynamic smem, BK=64 chunks ----------------
// g_xWb1[8192,1152] = Ah*Bh + Ah*Bl + Al*Bh. Virtual K = 3*8192, 384 chunks of 64.
// 128x128 CTA tile, 256 threads (2x4 warps, 64x32 each). Loop:
//   wait_group 1 -> barrier -> prefetch(c+2 -> stage (c+2)%3) -> compute(c)
// Stage = A(16KB) | B(16KB) = 32 KB, 128-byte rows, SW128 swizzle.
// 3 x 32768 = 98304 B DYNAMIC smem via cudaFuncSetAttribute (static 48K is
// the container-killer; dynamic is proven safe).
#define CHUNKS 384
#define GSTAGE 32768
#define GSMEM  (3 * GSTAGE)

__device__ __forceinline__ void hload(unsigned smBase, int st, int c,
                                      int bm, int bn, int tid) {
    int pass = c >> 7;
    int kk = (c & 127) << 6;
    const unsigned short* A = (pass < 2) ? g_Ah : g_Al;
    const unsigned short* B = (pass == 1) ? g_BlT : g_BhT;
    unsigned base = smBase + (unsigned)st * (unsigned)GSTAGE;
    #pragma unroll
    for (int i = 0; i < 4; i++) {
        int g = tid + i * 256;
        int row = g >> 3;
        int cc = (g & 7) * 16;
        unsigned so = swz128((unsigned)(row * 128 + cc));
        cp_async16(base + so,
                   (const char*)(A + (size_t)(bm + row) * NN + kk) + cc);
        cp_async16(base + 16384u + so,
                   (const char*)(B + (size_t)(bn + row) * NN + kk) + cc);
    }
}

__global__ void __launch_bounds__(256, 2) hmma_gemm1() {
    extern __shared__ __align__(1024) char gsm[];
    const int tid = threadIdx.x;
    const int wid = tid >> 5;
    const int lane = tid & 31;
    const int warpM = wid >> 2;
    const int warpN = wid & 3;
    const int bm = blockIdx.y * 128;
    const int bn = blockIdx.x * 128;
    const unsigned smBase = smem_u32(gsm);

    const int lq = lane >> 3;
    const int lr = lane & 7;
    const int aRow = warpM * 64 + lr + (lq & 1) * 8;
    const int aCol = (lq >> 1) * 16;
    const int bRow = warpN * 32 + (lq >> 1) * 8 + lr;
    const int bCol = (lq & 1) * 16;

    float acc[4][4][4];
    #pragma unroll
    for (int mi = 0; mi < 4; mi++) {
        #pragma unroll
        for (int ni = 0; ni < 4; ni++) {
            #pragma unroll
            for (int q = 0; q < 4; q++) {
                acc[mi][ni][q] = 0.f;
            }
        }
    }

    // prologue: stages 0 and 1 in flight
    hload(smBase, 0, 0, bm, bn, tid);
    cp_commit();
    hload(smBase, 1, 1, bm, bn, tid);
    cp_commit();

    int st = 0;
    for (int c = 0; c < CHUNKS; c++) {
        if (c + 1 < CHUNKS) {
            cp_wait1();
        } else {
            cp_wait0();
        }
        __syncthreads();
        if (c + 2 < CHUNKS) {
            int st2 = st + 2;
            if (st2 >= 3) {
                st2 -= 3;
            }
            hload(smBase, st2, c + 2, bm, bn, tid);
            cp_commit();
        }
        unsigned sA = smBase + (unsigned)st * (unsigned)GSTAGE;
        unsigned sB = sA + 16384u;
        #pragma unroll
        for (int ks = 0; ks < 4; ks++) {
            unsigned a[4][4];
            unsigned b[2][4];
            #pragma unroll
            for (int mi = 0; mi < 4; mi++) {
                ldmx4(a[mi][0], a[mi][1], a[mi][2], a[mi][3],
                      sA + swz128((unsigned)((aRow + mi * 16) * 128 + ks * 32 + aCol)));
            }
            #pragma unroll
            for (int nj = 0; nj < 2; nj++) {
                ldmx4(b[nj][0], b[nj][1], b[nj][2], b[nj][3],
                      sB + swz128((unsigned)((bRow + nj * 16) * 128 + ks * 32 + bCol)));
            }
            #pragma unroll
            for (int mi = 0; mi < 4; mi++) {
                #pragma unroll
                for (int ni = 0; ni < 4; ni++) {
                    mma16816(acc[mi][ni],
                             a[mi][0], a[mi][1], a[mi][2], a[mi][3],
                             b[ni >> 1][(ni & 1) * 2],
                             b[ni >> 1][(ni & 1) * 2 + 1]);
                }
            }
        }
        st = st + 1;
        if (st >= 3) {
            st = 0;
        }
    }

    #pragma unroll
    for (int mi = 0; mi < 4; mi++) {
        int row = bm + warpM * 64 + mi * 16 + (lane >> 2);
        #pragma unroll
        for (int ni = 0; ni < 4; ni++) {
            int col = bn + warpN * 32 + ni * 8 + (lane & 3) * 2;
            float2 v01;
            v01.x = acc[mi][ni][0];
            v01.y = acc[mi][ni][1];
            float2 v23;
            v23.x = acc[mi][ni][2];
            v23.y = acc[mi][ni][3];
            *(float2*)&g_xWb1[(size_t)row * W1COLS + col] = v01;
            *(float2*)&g_xWb1[(size_t)(row + 8) * W1COLS + col] = v23;
        }
    }
}

// ---------------- build Wbig2 = [comp2 x basis2 | root2 | 0pad] ----------------
__global__ void build_W2(const float* basis2, const float* comp2,
                         const float* root2) {
    __shared__ float sc[RR * NB];
    int tid = threadIdx.x;
    if (tid < RR * NB) {
        sc[tid] = comp2[tid];
    }
    __syncthreads();
    int idx = blockIdx.x * blockDim.x + tid;
    if (idx >= HH * OO) {
        return;
    }
    int k = idx >> 6;
    int o = idx & 63;
    float s[RR];
    #pragma unroll
    for (int r = 0; r < RR; r++) {
        s[r] = 0.f;
    }
    for (int b = 0; b < NB; b++) {
        float v = basis2[((size_t)b * HH + k) * OO + o];
        #pragma unroll
        for (int r = 0; r < RR; r++) {
            s[r] = fmaf(sc[r * NB + b], v, s[r]);
        }
    }
    float* orow = g_Wbig2 + (size_t)k * W2COLS;
    #pragma unroll
    for (int r = 0; r < RR; r++) {
        orow[r * OO + o] = s[r];
    }
    orow[RR * OO + o] = root2[(size_t)k * OO + o];
}

// ---------------- SIMT GEMM (layer 2), 128x128 tile, BK=16, f32x2 FMA ----------------
__global__ void __launch_bounds__(256, 2) sgemm_l2() {
    const float* A = g_h1;
    const float* B = g_Wbig2;
    float* C = g_xWb2;
    const int K = HH;
    const int lda = HH;
    const int ldb = W2COLS;
    const int ldc = W2COLS;
    __shared__ float As[16][132];
    __shared__ float Bs[16][128];

    const int tid = threadIdx.x;
    const int tx = tid & 15;
    const int ty = tid >> 4;
    const size_t bm = (size_t)blockIdx.y * 128;
    const size_t bn = (size_t)blockIdx.x * 128;

    const int arow = tid >> 2;
    const int acol = (tid & 3) * 4;
    const float* Ap = A + (bm + arow) * (size_t)lda + acol;
    const int brow = tid >> 5;
    const int bcol = (tid & 31) * 4;
    const float* Bp = B + (size_t)brow * ldb + bn + bcol;

    unsigned long long acc[8][4];
    #pragma unroll
    for (int i = 0; i < 8; i++) {
        #pragma unroll
        for (int j = 0; j < 4; j++) {
            acc[i][j] = 0ull;
        }
    }

    for (int k0 = 0; k0 < K; k0 += 16) {
        float4 a0 = *(const float4*)(Ap + k0);
        float4 a1 = *(const float4*)(Ap + (size_t)64 * lda + k0);
        float4 b0 = *(const float4*)(Bp + (size_t)k0 * ldb);
        float4 b1 = *(const float4*)(Bp + (size_t)(k0 + 8) * ldb);
        __syncthreads();
        As[acol + 0][arow] = a0.x;
        As[acol + 1][arow] = a0.y;
        As[acol + 2][arow] = a0.z;
        As[acol + 3][arow] = a0.w;
        As[acol + 0][arow + 64] = a1.x;
        As[acol + 1][arow + 64] = a1.y;
        As[acol + 2][arow + 64] = a1.z;
        As[acol + 3][arow + 64] = a1.w;
        *(float4*)&Bs[brow][bcol] = b0;
        *(float4*)&Bs[brow + 8][bcol] = b1;
        __syncthreads();
        #pragma unroll
        for (int k = 0; k < 16; k++) {
            float4 aA = *(const float4*)&As[k][ty * 8];
            float4 aB = *(const float4*)&As[k][ty * 8 + 4];
            ulonglong2 blo = *(const ulonglong2*)&Bs[k][tx * 8];
            ulonglong2 bhi = *(const ulonglong2*)&Bs[k][tx * 8 + 4];
            float av[8];
            av[0] = aA.x; av[1] = aA.y; av[2] = aA.z; av[3] = aA.w;
            av[4] = aB.x; av[5] = aB.y; av[6] = aB.z; av[7] = aB.w;
            unsigned long long bv[4];
            bv[0] = blo.x; bv[1] = blo.y; bv[2] = bhi.x; bv[3] = bhi.y;
            #pragma unroll
            for (int i = 0; i < 8; i++) {
                unsigned long long ad = dup2(av[i]);
                #pragma unroll
                for (int j = 0; j < 4; j++) {
                    acc[i][j] = ffma2(ad, bv[j], acc[i][j]);
                }
            }
        }
    }
    #pragma unroll
    for (int i = 0; i < 8; i++) {
        float* crow = C + (bm + ty * 8 + i) * (size_t)ldc + bn + tx * 8;
        ulonglong2 s0;
        s0.x = acc[i][0];
        s0.y = acc[i][1];
        ulonglong2 s1;
        s1.x = acc[i][2];
        s1.y = acc[i][3];
        *(ulonglong2*)(crow) = s0;
        *(ulonglong2*)(crow + 4) = s1;
    }
}

// ---------------- edge count per (dst, relation) segment ----------------
__global__ void count_edges(const void* ei, const void* et, int E) {
    int e = blockIdx.x * blockDim.x + threadIdx.x;
    if (e >= E) {
        return;
    }
    int dst = load_idx(ei, (long long)E + e) & (NN - 1);
    int r = load_idx(et, e) & (RR - 1);
    atomicAdd(&g_cnt[dst * RR + r], 1);
}

// ---------------- scatter layer 1: warp per edge, red.v4 per lane ----------------
__global__ void scatter1(const void* ei, const void* et, int E) {
    int gt = blockIdx.x * blockDim.x + threadIdx.x;
    int e = gt >> 5;
    int lane = gt & 31;
    if (e >= E) {
        return;
    }
    int src = load_idx(ei, e) & (NN - 1);
    int dst = load_idx(ei, (long long)E + e) & (NN - 1);
    int r = load_idx(et, e) & (RR - 1);
    float4 v = *(const float4*)(g_xWb1 + (size_t)src * W1COLS + r * HH + lane * 4);
    float* d = g_sums1 + ((size_t)(dst * RR + r)) * HH + lane * 4;
    red_add_v4(d, v);
}

// ---------------- combine layer 1: mean + root + bias + relu ----------------
__global__ void combine1(const float* bias1) {
    int idx = blockIdx.x * blockDim.x + threadIdx.x;
    int n = idx >> 7;
    int h = idx & 127;
    float s = 0.f;
    #pragma unroll
    for (int r = 0; r < RR; r++) {
        int seg = n * RR + r;
        int c = g_cnt[seg];
        float inv = 1.f / (float)(c > 1 ? c : 1);
        s += g_sums1[(size_t)seg * HH + h] * inv;
    }
    s += g_xWb1[(size_t)n * W1COLS + RR * HH + h] + bias1[h];
    g_h1[idx] = fmaxf(s, 0.f);
}

// ---------------- scatter layer 2: warp per edge, red.v2 per lane ----------------
__global__ void scatter2(const void* ei, const void* et, int E) {
    int gt = blockIdx.x * blockDim.x + threadIdx.x;
    int e = gt >> 5;
    int lane = gt & 31;
    if (e >= E) {
        return;
    }
    int src = load_idx(ei, e) & (NN - 1);
    int dst = load_idx(ei, (long long)E + e) & (NN - 1);
    int r = load_idx(et, e) & (RR - 1);
    float2 v = *(const float2*)(g_xWb2 + (size_t)src * W2COLS + r * OO + lane * 2);
    float* d = g_sums2 + ((size_t)(dst * RR + r)) * OO + lane * 2;
    red_add_v2(d, v);
}

// ---------------- combine layer 2: mean + root + bias ----------------
__global__ void combine2(const float* bias2) {
    int idx = blockIdx.x * blockDim.x + threadIdx.x;
    int n = idx >> 6;
    int o = idx & 63;
    float s = 0.f;
    #pragma unroll
    for (int r = 0; r < RR; r++) {
        int seg = n * RR + r;
        int c = g_cnt[seg];
        float inv = 1.f / (float)(c > 1 ? c : 1);
        s += g_sums2[(size_t)seg * OO + o] * inv;
    }
    s += g_xWb2[(size_t)n * W2COLS + RR * OO + o] + bias2[o];
    g_h2[idx] = s;
}

// ---------------- classifier ----------------
__global__ void classifier(const float* w, const float* b, float* out) {
    __shared__ float hrow[OO];
    int n = blockIdx.x;
    int c = threadIdx.x;
    if (c < OO) {
        hrow[c] = g_h2[(size_t)n * OO + c];
    }
    __syncthreads();
    float acc = b[c];
    #pragma unroll
    for (int o = 0; o < OO; o++) {
        acc = fmaf(hrow[o], w[o * CC + c], acc);
    }
    out[(size_t)n * CC + c] = acc;
}

// ---------------- launch ----------------
// hmma_gemm1 stays 4th so the ncu capture window profiles it.
extern "C" void kernel_launch(void* const* d_in, const int* in_sizes, int n_in,
                              void* d_out, int out_size) {
    const float* x      = (const float*)d_in[0];
    const void*  ei     = d_in[1];
    const void*  et     = d_in[2];
    const float* basis1 = (const float*)d_in[3];
    const float* comp1  = (const float*)d_in[4];
    const float* root1  = (const float*)d_in[5];
    const float* bias1  = (const float*)d_in[6];
    const float* basis2 = (const float*)d_in[7];
    const float* comp2  = (const float*)d_in[8];
    const float* root2  = (const float*)d_in[9];
    const float* bias2  = (const float*)d_in[10];
    const float* clfw   = (const float*)d_in[11];
    const float* clfb   = (const float*)d_in[12];
    float* out = (float*)d_out;
    const int E = in_sizes[2];

    // idempotent, deterministic, no allocation; needed for 98304 B dynamic smem
    cudaFuncSetAttribute(hmma_gemm1,
                         cudaFuncAttributeMaxDynamicSharedMemorySize, GSMEM);

    splitX<<<(int)(((size_t)NN * NN / 4) / 256), 256>>>(x);
    build_W1<<<NN * HH / 256, 256>>>(basis1, comp1, root1);
    splitW1<<<dim3(W1COLS / 32, NN / 32), dim3(32, 8)>>>();
    hmma_gemm1<<<dim3(W1COLS / 128, NN / 128), 256, GSMEM>>>();

    zero_all<<<(NSEG * HH / 4 + 255) / 256, 256>>>();
    detect_dtype<<<(2 * E + 255) / 256, 256>>>((const unsigned*)ei, 2 * E);
    count_edges<<<(E + 255) / 256, 256>>>(ei, et, E);

    scatter1<<<(E * 32 + 255) / 256, 256>>>(ei, et, E);
    combine1<<<NN * HH / 256, 256>>>(bias1);

    build_W2<<<(HH * OO + 255) / 256, 256>>>(basis2, comp2, root2);
    sgemm_l2<<<dim3(W2COLS / 128, NN / 128), 256>>>();
    scatter2<<<(E * 32 + 255) / 256, 256>>>(ei, et, E);
    combine2<<<NN * OO / 256, 256>>>(bias2);

    classifier<<<NN, CC>>>(clfw, clfb, out);
}